// round 3
// baseline (speedup 1.0000x reference)
#include <cuda_runtime.h>

// ---------------------------------------------------------------------------
// TeamMovementModel: two LSTMs (H=128, T=128) + FC.
// R3: lstm split into 3 chunk launches (ncu visibility on the real kernel),
// tanh.approx activations (halve MUFU + issue pressure), KSM=80/KRG=48.
// ---------------------------------------------------------------------------

#define Hh       128
#define GATES    512
#define Tt       128
#define Mseq     10
#define KSM      80           // k-rows of W^T in smem (even)
#define KRG      48           // k-rows of W^T in registers (even)
#define NPLAYER  1408
#define NBALL    64
#define PCTAS    141
#define NCTAS    148
#define THREADS  256
#define GPS      22           // gate-pair stride: [j/2][parity][10] padded to 22

// smem (floats): Wt [KSM/2][512][2] | g_s [256][22] | h_s [128][10] | x_s [256][10]
#define SM_WT   0
#define SM_G    (KSM * GATES)                     // 40960
#define SM_H    (SM_G + 256 * GPS)                // 46592
#define SM_X    (SM_H + Hh * Mseq)                // 47872
#define SM_FLOATS (SM_X + 256 * Mseq)             // 50432
#define SM_BYTES  (SM_FLOATS * 4)                 // 201728

__device__ float g_hid [(NPLAYER + NBALL) * Hh];  // final hidden states
__device__ float g_hsav[NCTAS * Hh * Mseq];       // h state between chunks
__device__ float g_csav[NCTAS * Hh * Mseq];       // c state between chunks

typedef unsigned long long u64;

__device__ __forceinline__ u64 splat2(float x) {
    u64 r; unsigned int u = __float_as_uint(x);
    asm("mov.b64 %0, {%1, %1};" : "=l"(r) : "r"(u));
    return r;
}
__device__ __forceinline__ u64 pack2(float lo, float hi) {
    u64 r;
    asm("mov.b64 %0, {%1, %2};" : "=l"(r)
        : "r"(__float_as_uint(lo)), "r"(__float_as_uint(hi)));
    return r;
}
__device__ __forceinline__ void unpack2(u64 v, float& lo, float& hi) {
    unsigned int a, b;
    asm("mov.b64 {%0, %1}, %2;" : "=r"(a), "=r"(b) : "l"(v));
    lo = __uint_as_float(a); hi = __uint_as_float(b);
}
__device__ __forceinline__ void ffma2(u64& d, u64 a, u64 b) {
    asm("fma.rn.f32x2 %0, %1, %2, %0;" : "+l"(d) : "l"(a), "l"(b));
}

// HW tanh approximation (sm_75+): 1 MUFU op.
__device__ __forceinline__ float tanhap(float x) {
    float y; asm("tanh.approx.f32 %0, %1;" : "=f"(y) : "f"(x)); return y;
}
__device__ __forceinline__ float sigap(float x) {
    return fmaf(0.5f, tanhap(0.5f * x), 0.5f);
}

// One k-pair (k=2*k2, 2*k2+1) of the recurrent GEMM for both gate columns.
#define MMA_PAIR(HPTR, W00, W01, W10, W11) do {                                \
    const ulonglong2* hv = (const ulonglong2*)(HPTR);                          \
    ulonglong2 A = hv[0], B = hv[1], C = hv[2], D = hv[3], E = hv[4];          \
    u64 s00 = splat2(W00), s01 = splat2(W01);                                  \
    u64 s10 = splat2(W10), s11 = splat2(W11);                                  \
    ffma2(acc0[0], A.x, s00); ffma2(acc1[0], A.x, s10);                        \
    ffma2(acc0[1], A.y, s00); ffma2(acc1[1], A.y, s10);                        \
    ffma2(acc0[2], B.x, s00); ffma2(acc1[2], B.x, s10);                        \
    ffma2(acc0[3], B.y, s00); ffma2(acc1[3], B.y, s10);                        \
    ffma2(acc0[4], C.x, s00); ffma2(acc1[4], C.x, s10);                        \
    ffma2(acc0[0], C.y, s01); ffma2(acc1[0], C.y, s11);                        \
    ffma2(acc0[1], D.x, s01); ffma2(acc1[1], D.x, s11);                        \
    ffma2(acc0[2], D.y, s01); ffma2(acc1[2], D.y, s11);                        \
    ffma2(acc0[3], E.x, s01); ffma2(acc1[3], E.x, s11);                        \
    ffma2(acc0[4], E.y, s01); ffma2(acc1[4], E.y, s11);                        \
} while (0)

__global__ __launch_bounds__(THREADS, 1)
void lstm_chunk(const float* __restrict__ xp, const float* __restrict__ xb,
                const float* __restrict__ p_wih, const float* __restrict__ p_whh,
                const float* __restrict__ p_bih, const float* __restrict__ p_bhh,
                const float* __restrict__ b_wih, const float* __restrict__ b_whh,
                const float* __restrict__ b_bih, const float* __restrict__ b_bhh,
                int step0, int step1)
{
    extern __shared__ float sm[];
    float* Wt  = sm + SM_WT;   // [k2][j][parity]
    float* g_s = sm + SM_G;    // [j>>1][j&1][m], pair stride 22
    float* h_s = sm + SM_H;    // [k][m] stride 10
    float* x_s = sm + SM_X;    // [(t*2+d)][m] stride 10

    const int tid = threadIdx.x;
    const int cta = blockIdx.x;
    const bool is_ball = (cta >= PCTAS);

    const float* wih   = is_ball ? b_wih : p_wih;
    const float* whh   = is_ball ? b_whh : p_whh;
    const float* bih   = is_ball ? b_bih : p_bih;
    const float* bhh   = is_ball ? b_bhh : p_bhh;
    const float* xbase = is_ball ? xb : xp;
    const int seq0  = is_ball ? (cta - PCTAS) * Mseq : cta * Mseq;
    const int ntot  = is_ball ? NBALL : NPLAYER;
    const int Mact  = min(Mseq, ntot - seq0);
    const int gbase = is_ball ? NPLAYER : 0;

    // --- Wt smem fill: pair-interleaved transpose ---
    for (int idx = tid; idx < GATES * KSM; idx += THREADS) {
        int j  = idx / KSM;
        int kk = idx - j * KSM;
        Wt[((kk >> 1) * GATES + j) * 2 + (kk & 1)] = whh[j * Hh + kk];
    }
    // --- h state: zero (first chunk) or restore ---
    if (step0 == 0) {
        for (int idx = tid; idx < Hh * Mseq; idx += THREADS) h_s[idx] = 0.0f;
    } else {
        for (int idx = tid; idx < Hh * Mseq; idx += THREADS)
            h_s[idx] = g_hsav[cta * (Hh * Mseq) + idx];
    }
    // --- x tile, transposed to [(t,d)][m] ---
    for (int m = 0; m < Mseq; m++) {
        x_s[tid * Mseq + m] = (m < Mact) ? xbase[(seq0 + m) * 256 + tid] : 0.0f;
    }

    // --- per-thread constants: gate columns j0 = 2*tid, j1 = 2*tid+1 ---
    const int j0 = 2 * tid, j1 = 2 * tid + 1;
    const u64 bias0p = splat2(bih[j0] + bhh[j0]);
    const u64 bias1p = splat2(bih[j1] + bhh[j1]);
    const u64 wi00p = splat2(wih[j0 * 2 + 0]), wi01p = splat2(wih[j0 * 2 + 1]);
    const u64 wi10p = splat2(wih[j1 * 2 + 0]), wi11p = splat2(wih[j1 * 2 + 1]);
    const bool is_tanh_gate = (tid >= 128) && (tid < 192);   // g-gate columns

    // register tail of W^T (k = KSM..127)
    float wr0[KRG], wr1[KRG];
    #pragma unroll
    for (int kk = 0; kk < KRG; kk++) {
        wr0[kk] = whh[j0 * Hh + KSM + kk];
        wr1[kk] = whh[j1 * Hh + KSM + kk];
    }

    // --- c state: zero or restore (thread-owned, indexed by e = q*256+tid) ---
    float c[5];
    #pragma unroll
    for (int q = 0; q < 5; q++) {
        c[q] = (step0 == 0) ? 0.0f
             : g_csav[cta * (Hh * Mseq) + q * THREADS + tid];
    }

    __syncthreads();

    for (int step = step0; step < step1; step++) {
        // ---- init accumulators: bias + input projection ----
        u64 acc0[5], acc1[5];
        const float* xr0 = x_s + (2 * step) * Mseq;
        const float* xr1 = x_s + (2 * step + 1) * Mseq;
        #pragma unroll
        for (int q = 0; q < 5; q++) {
            u64 X0 = *(const u64*)(xr0 + 2 * q);
            u64 X1 = *(const u64*)(xr1 + 2 * q);
            u64 a0 = bias0p, a1 = bias1p;
            ffma2(a0, X0, wi00p); ffma2(a0, X1, wi01p);
            ffma2(a1, X0, wi10p); ffma2(a1, X1, wi11p);
            acc0[q] = a0; acc1[q] = a1;
        }

        // ---- recurrent GEMM: smem-weight pairs ----
        #pragma unroll 4
        for (int k2 = 0; k2 < KSM / 2; k2++) {
            float4 wv = *(const float4*)(Wt + (k2 * GATES) * 2 + 4 * tid);
            MMA_PAIR(h_s + k2 * 2 * Mseq, wv.x, wv.y, wv.z, wv.w);
        }
        // ---- recurrent GEMM: register-weight tail ----
        #pragma unroll
        for (int kk2 = 0; kk2 < KRG / 2; kk2++) {
            MMA_PAIR(h_s + (KSM + 2 * kk2) * Mseq,
                     wr0[2 * kk2], wr0[2 * kk2 + 1],
                     wr1[2 * kk2], wr1[2 * kk2 + 1]);
        }

        // ---- producer-side activations (warp-uniform gate type) + scatter ----
        float* g0 = g_s + tid * GPS;
        float* g1 = g_s + tid * GPS + Mseq;
        if (is_tanh_gate) {
            #pragma unroll
            for (int q = 0; q < 5; q++) {
                float a0, a1, b0, b1;
                unpack2(acc0[q], a0, a1); unpack2(acc1[q], b0, b1);
                *(u64*)(g0 + 2 * q) = pack2(tanhap(a0), tanhap(a1));
                *(u64*)(g1 + 2 * q) = pack2(tanhap(b0), tanhap(b1));
            }
        } else {
            #pragma unroll
            for (int q = 0; q < 5; q++) {
                float a0, a1, b0, b1;
                unpack2(acc0[q], a0, a1); unpack2(acc1[q], b0, b1);
                *(u64*)(g0 + 2 * q) = pack2(sigap(a0), sigap(a1));
                *(u64*)(g1 + 2 * q) = pack2(sigap(b0), sigap(b1));
            }
        }
        __syncthreads();

        // ---- cell update: c = f*c + i*g ; h = o*tanh(c) ----
        #pragma unroll
        for (int q = 0; q < 5; q++) {
            const int e = q * THREADS + tid;
            const int u = e / Mseq;
            const int m = e - u * Mseq;
            const int ib = (u >> 1) * GPS + (u & 1) * Mseq + m;
            const float fi = g_s[ib];
            const float ff = g_s[ib + 64 * GPS];
            const float fg = g_s[ib + 128 * GPS];
            const float fo = g_s[ib + 192 * GPS];
            c[q] = ff * c[q] + fi * fg;
            h_s[u * Mseq + m] = fo * tanhap(c[q]);
        }
        __syncthreads();
    }

    // ---- save state for next chunk ----
    for (int idx = tid; idx < Hh * Mseq; idx += THREADS)
        g_hsav[cta * (Hh * Mseq) + idx] = h_s[idx];
    #pragma unroll
    for (int q = 0; q < 5; q++)
        g_csav[cta * (Hh * Mseq) + q * THREADS + tid] = c[q];

    // ---- final chunk: write final hidden states ----
    if (step1 == Tt) {
        #pragma unroll
        for (int q = 0; q < 5; q++) {
            const int e = q * THREADS + tid;
            const int u = e / Mseq;
            const int m = e - u * Mseq;
            if (m < Mact)
                g_hid[(gbase + seq0 + m) * Hh + u] = h_s[u * Mseq + m];
        }
    }
}

// FC: 128 blocks = (batch b, half of 22 players). fc_w + hidden states in smem.
#define FC_THREADS 448
__global__ __launch_bounds__(FC_THREADS)
void fc_kernel(const float* __restrict__ fc_w,
               const float* __restrict__ fc_b,
               float* __restrict__ out)
{
    __shared__ float fw[40 * 258];
    __shared__ float ph[11 * 128];
    __shared__ float ball[128];

    const int bx   = blockIdx.x;
    const int b    = bx >> 1;
    const int half = bx & 1;
    const int tid  = threadIdx.x;

    for (int idx = tid; idx < 40 * 256; idx += FC_THREADS) {
        int j = idx >> 8, k = idx & 255;
        fw[j * 258 + k] = fc_w[idx];
    }
    for (int idx = tid; idx < 11 * 128; idx += FC_THREADS) {
        int p = idx >> 7, k = idx & 127;
        ph[idx] = g_hid[(b * 22 + half * 11 + p) * Hh + k];
    }
    for (int idx = tid; idx < 128; idx += FC_THREADS)
        ball[idx] = g_hid[(NPLAYER + b) * Hh + idx];
    __syncthreads();

    if (tid < 440) {
        const int p = tid / 40;
        const int j = tid - p * 40;
        const float2* php  = (const float2*)(ph + p * 128);
        const float2* blp  = (const float2*)(ball);
        const float2* fwp0 = (const float2*)(fw + j * 258);
        const float2* fwp1 = (const float2*)(fw + j * 258 + 128);
        float acc = fc_b[j];
        #pragma unroll 8
        for (int k2 = 0; k2 < 64; k2++) {
            float2 hp = php[k2], hb = blp[k2];
            float2 w0 = fwp0[k2], w1 = fwp1[k2];
            acc += hp.x * w0.x + hp.y * w0.y + hb.x * w1.x + hb.y * w1.y;
        }
        out[(b * 22 + half * 11 + p) * 40 + j] = acc;
    }
}

extern "C" void kernel_launch(void* const* d_in, const int* in_sizes, int n_in,
                              void* d_out, int out_size)
{
    const float* xp    = (const float*)d_in[0];
    const float* xb    = (const float*)d_in[1];
    const float* p_wih = (const float*)d_in[2];
    const float* p_whh = (const float*)d_in[3];
    const float* p_bih = (const float*)d_in[4];
    const float* p_bhh = (const float*)d_in[5];
    const float* b_wih = (const float*)d_in[6];
    const float* b_whh = (const float*)d_in[7];
    const float* b_bih = (const float*)d_in[8];
    const float* b_bhh = (const float*)d_in[9];
    const float* fc_w  = (const float*)d_in[10];
    const float* fc_b  = (const float*)d_in[11];
    float* out = (float*)d_out;

    cudaFuncSetAttribute(lstm_chunk,
                         cudaFuncAttributeMaxDynamicSharedMemorySize, SM_BYTES);

    // 3 chunks -> launch pattern [L,L,L,F]; ncu (-s 5 -c 1) captures a mid
    // lstm chunk instead of fc_kernel.
    lstm_chunk<<<NCTAS, THREADS, SM_BYTES>>>(xp, xb, p_wih, p_whh, p_bih, p_bhh,
                                             b_wih, b_whh, b_bih, b_bhh, 0, 43);
    lstm_chunk<<<NCTAS, THREADS, SM_BYTES>>>(xp, xb, p_wih, p_whh, p_bih, p_bhh,
                                             b_wih, b_whh, b_bih, b_bhh, 43, 86);
    lstm_chunk<<<NCTAS, THREADS, SM_BYTES>>>(xp, xb, p_wih, p_whh, p_bih, p_bhh,
                                             b_wih, b_whh, b_bih, b_bhh, 86, Tt);
    fc_kernel<<<128, FC_THREADS>>>(fc_w, fc_b, out);
}

// round 4
// speedup vs baseline: 1.1298x; 1.1298x over previous
#include <cuda_runtime.h>

// ---------------------------------------------------------------------------
// TeamMovementModel: two LSTMs (H=128, T=128) + FC.
// R4: single lstm kernel; lane-parallel-K f32x2 GEMM (f32x2 lanes hold
// even/odd k partial sums -> zero splat MOVs in hot loop); tanh.approx
// activations (proven rel_err 1.8e-6 in R3).
// ---------------------------------------------------------------------------

#define Hh       128
#define GATES    512
#define Tt       128
#define Mseq     10
#define KSM      94           // k-rows of W^T in smem (even)
#define KRG      34           // k-rows of W^T in registers (even)
#define NPLAYER  1408
#define NBALL    64
#define PCTAS    141
#define NCTAS    148
#define THREADS  256
#define GPS      22           // gate-pair stride for g_s

// smem (floats): Wt [KSM/2][512][2] | g_s [256][22] | h2 [64][10][2] | x_s [256][10]
#define SM_WT   0
#define SM_G    (KSM * GATES)                     // 48128
#define SM_H    (SM_G + 256 * GPS)                // 53760
#define SM_X    (SM_H + Hh * Mseq)                // 55040
#define SM_FLOATS (SM_X + 256 * Mseq)             // 57600
#define SM_BYTES  (SM_FLOATS * 4)                 // 230400

__device__ float g_hid[(NPLAYER + NBALL) * Hh];

typedef unsigned long long u64;

__device__ __forceinline__ u64 pack2(float lo, float hi) {
    u64 r;
    asm("mov.b64 %0, {%1, %2};" : "=l"(r)
        : "r"(__float_as_uint(lo)), "r"(__float_as_uint(hi)));
    return r;
}
__device__ __forceinline__ void unpack2(u64 v, float& lo, float& hi) {
    unsigned int a, b;
    asm("mov.b64 {%0, %1}, %2;" : "=r"(a), "=r"(b) : "l"(v));
    lo = __uint_as_float(a); hi = __uint_as_float(b);
}
__device__ __forceinline__ void ffma2(u64& d, u64 a, u64 b) {
    asm("fma.rn.f32x2 %0, %1, %2, %0;" : "+l"(d) : "l"(a), "l"(b));
}

// HW tanh approximation (1 MUFU op).
__device__ __forceinline__ float tanhap(float x) {
    float y; asm("tanh.approx.f32 %0, %1;" : "=f"(y) : "f"(x)); return y;
}
__device__ __forceinline__ float sigap(float x) {
    return fmaf(0.5f, tanhap(0.5f * x), 0.5f);
}

// One k-pair of the recurrent GEMM, both gate columns, lanes = (even k, odd k).
// HB: &h2[k2][0][0] (20 contiguous floats = 5 u64, one per 2 sequences... one
// u64 per sequence m: {h(k0,m), h(k1,m)}).
#define MMA_PAIR2(HB, W0, W1) do {                                             \
    const ulonglong2* hv = (const ulonglong2*)(HB);                            \
    ulonglong2 A = hv[0], B = hv[1], C = hv[2], D = hv[3], E = hv[4];          \
    ffma2(acc0[0], A.x, (W0)); ffma2(acc1[0], A.x, (W1));                      \
    ffma2(acc0[1], A.y, (W0)); ffma2(acc1[1], A.y, (W1));                      \
    ffma2(acc0[2], B.x, (W0)); ffma2(acc1[2], B.x, (W1));                      \
    ffma2(acc0[3], B.y, (W0)); ffma2(acc1[3], B.y, (W1));                      \
    ffma2(acc0[4], C.x, (W0)); ffma2(acc1[4], C.x, (W1));                      \
    ffma2(acc0[5], C.y, (W0)); ffma2(acc1[5], C.y, (W1));                      \
    ffma2(acc0[6], D.x, (W0)); ffma2(acc1[6], D.x, (W1));                      \
    ffma2(acc0[7], D.y, (W0)); ffma2(acc1[7], D.y, (W1));                      \
    ffma2(acc0[8], E.x, (W0)); ffma2(acc1[8], E.x, (W1));                      \
    ffma2(acc0[9], E.y, (W0)); ffma2(acc1[9], E.y, (W1));                      \
} while (0)

__global__ __launch_bounds__(THREADS, 1)
void lstm_kernel(const float* __restrict__ xp, const float* __restrict__ xb,
                 const float* __restrict__ p_wih, const float* __restrict__ p_whh,
                 const float* __restrict__ p_bih, const float* __restrict__ p_bhh,
                 const float* __restrict__ b_wih, const float* __restrict__ b_whh,
                 const float* __restrict__ b_bih, const float* __restrict__ b_bhh)
{
    extern __shared__ float sm[];
    float* Wt  = sm + SM_WT;   // [k2][j][parity]
    float* g_s = sm + SM_G;    // [j>>1][j&1][m], pair stride 22
    float* h2  = sm + SM_H;    // [k2][m][parity] : k2*20 + 2m + (k&1)
    float* x_s = sm + SM_X;    // [(t*2+d)][m] stride 10

    const int tid = threadIdx.x;
    const int cta = blockIdx.x;
    const bool is_ball = (cta >= PCTAS);

    const float* wih   = is_ball ? b_wih : p_wih;
    const float* whh   = is_ball ? b_whh : p_whh;
    const float* bih   = is_ball ? b_bih : p_bih;
    const float* bhh   = is_ball ? b_bhh : p_bhh;
    const float* xbase = is_ball ? xb : xp;
    const int seq0  = is_ball ? (cta - PCTAS) * Mseq : cta * Mseq;
    const int ntot  = is_ball ? NBALL : NPLAYER;
    const int Mact  = min(Mseq, ntot - seq0);
    const int gbase = is_ball ? NPLAYER : 0;

    // --- Wt smem fill: pair-interleaved transpose ---
    for (int idx = tid; idx < GATES * KSM; idx += THREADS) {
        int j  = idx / KSM;
        int kk = idx - j * KSM;
        Wt[((kk >> 1) * GATES + j) * 2 + (kk & 1)] = whh[j * Hh + kk];
    }
    // --- zero h ---
    for (int idx = tid; idx < Hh * Mseq; idx += THREADS) h2[idx] = 0.0f;
    // --- x tile, transposed to [(t,d)][m] ---
    for (int m = 0; m < Mseq; m++) {
        x_s[tid * Mseq + m] = (m < Mact) ? xbase[(seq0 + m) * 256 + tid] : 0.0f;
    }

    // --- per-thread constants: gate columns j0 = 2*tid, j1 = 2*tid+1 ---
    const int j0 = 2 * tid, j1 = 2 * tid + 1;
    const float bias0 = bih[j0] + bhh[j0];
    const float bias1 = bih[j1] + bhh[j1];
    const float wi00 = wih[j0 * 2 + 0], wi01 = wih[j0 * 2 + 1];
    const float wi10 = wih[j1 * 2 + 0], wi11 = wih[j1 * 2 + 1];
    const bool is_tanh_gate = (tid >= 128) && (tid < 192);   // g-gate columns

    // register tail of W^T, pre-packed as k-pairs (zero MOVs in the loop)
    u64 wr0p[KRG / 2], wr1p[KRG / 2];
    #pragma unroll
    for (int i = 0; i < KRG / 2; i++) {
        wr0p[i] = pack2(whh[j0 * Hh + KSM + 2 * i], whh[j0 * Hh + KSM + 2 * i + 1]);
        wr1p[i] = pack2(whh[j1 * Hh + KSM + 2 * i], whh[j1 * Hh + KSM + 2 * i + 1]);
    }

    float c[5] = {0.f, 0.f, 0.f, 0.f, 0.f};

    __syncthreads();

    for (int step = 0; step < Tt; step++) {
        // ---- init accumulators: lane0 = bias + x-proj, lane1 = 0 ----
        u64 acc0[10], acc1[10];
        const float* xr = x_s + step * 2 * Mseq;   // x0[0..9], x1[0..9]
        #pragma unroll
        for (int m = 0; m < Mseq; m++) {
            const float x0 = xr[m], x1 = xr[Mseq + m];
            acc0[m] = pack2(fmaf(wi01, x1, fmaf(wi00, x0, bias0)), 0.0f);
            acc1[m] = pack2(fmaf(wi11, x1, fmaf(wi10, x0, bias1)), 0.0f);
        }

        // ---- recurrent GEMM: smem-weight k-pairs ----
        #pragma unroll 4
        for (int k2 = 0; k2 < KSM / 2; k2++) {
            ulonglong2 wv = *(const ulonglong2*)(Wt + k2 * (GATES * 2) + 4 * tid);
            MMA_PAIR2(h2 + k2 * 20, wv.x, wv.y);
        }
        // ---- recurrent GEMM: register-weight tail ----
        #pragma unroll
        for (int i = 0; i < KRG / 2; i++) {
            MMA_PAIR2(h2 + (KSM / 2 + i) * 20, wr0p[i], wr1p[i]);
        }

        // ---- reduce lanes, apply activation (warp-uniform), scatter ----
        float* g0 = g_s + tid * GPS;
        float* g1 = g0 + Mseq;
        if (is_tanh_gate) {
            #pragma unroll
            for (int q = 0; q < 5; q++) {
                float a0, a1, b0, b1, e0, e1, f0, f1;
                unpack2(acc0[2 * q], a0, a1); unpack2(acc0[2 * q + 1], b0, b1);
                unpack2(acc1[2 * q], e0, e1); unpack2(acc1[2 * q + 1], f0, f1);
                *(u64*)(g0 + 2 * q) = pack2(tanhap(a0 + a1), tanhap(b0 + b1));
                *(u64*)(g1 + 2 * q) = pack2(tanhap(e0 + e1), tanhap(f0 + f1));
            }
        } else {
            #pragma unroll
            for (int q = 0; q < 5; q++) {
                float a0, a1, b0, b1, e0, e1, f0, f1;
                unpack2(acc0[2 * q], a0, a1); unpack2(acc0[2 * q + 1], b0, b1);
                unpack2(acc1[2 * q], e0, e1); unpack2(acc1[2 * q + 1], f0, f1);
                *(u64*)(g0 + 2 * q) = pack2(sigap(a0 + a1), sigap(b0 + b1));
                *(u64*)(g1 + 2 * q) = pack2(sigap(e0 + e1), sigap(f0 + f1));
            }
        }
        __syncthreads();

        // ---- cell update: c = f*c + i*g ; h = o*tanh(c) ----
        #pragma unroll
        for (int q = 0; q < 5; q++) {
            const int e = q * THREADS + tid;     // 0..1279
            const int u = e / Mseq;
            const int m = e - u * Mseq;
            const int ib = (u >> 1) * GPS + (u & 1) * Mseq + m;
            const float fi = g_s[ib];
            const float ff = g_s[ib + 64 * GPS];
            const float fg = g_s[ib + 128 * GPS];
            const float fo = g_s[ib + 192 * GPS];
            c[q] = ff * c[q] + fi * fg;
            h2[(u >> 1) * 20 + 2 * m + (u & 1)] = fo * tanhap(c[q]);
        }
        __syncthreads();
    }

    // ---- write final hidden states ----
    #pragma unroll
    for (int q = 0; q < 5; q++) {
        const int e = q * THREADS + tid;
        const int u = e / Mseq;
        const int m = e - u * Mseq;
        if (m < Mact)
            g_hid[(gbase + seq0 + m) * Hh + u] = h2[(u >> 1) * 20 + 2 * m + (u & 1)];
    }
}

// FC: 128 blocks = (batch b, half of 22 players). fc_w + hidden states in smem.
#define FC_THREADS 448
__global__ __launch_bounds__(FC_THREADS)
void fc_kernel(const float* __restrict__ fc_w,
               const float* __restrict__ fc_b,
               float* __restrict__ out)
{
    __shared__ float fw[40 * 258];
    __shared__ float ph[11 * 128];
    __shared__ float ball[128];

    const int bx   = blockIdx.x;
    const int b    = bx >> 1;
    const int half = bx & 1;
    const int tid  = threadIdx.x;

    for (int idx = tid; idx < 40 * 256; idx += FC_THREADS) {
        int j = idx >> 8, k = idx & 255;
        fw[j * 258 + k] = fc_w[idx];
    }
    for (int idx = tid; idx < 11 * 128; idx += FC_THREADS) {
        int p = idx >> 7, k = idx & 127;
        ph[idx] = g_hid[(b * 22 + half * 11 + p) * Hh + k];
    }
    for (int idx = tid; idx < 128; idx += FC_THREADS)
        ball[idx] = g_hid[(NPLAYER + b) * Hh + idx];
    __syncthreads();

    if (tid < 440) {
        const int p = tid / 40;
        const int j = tid - p * 40;
        const float2* php  = (const float2*)(ph + p * 128);
        const float2* blp  = (const float2*)(ball);
        const float2* fwp0 = (const float2*)(fw + j * 258);
        const float2* fwp1 = (const float2*)(fw + j * 258 + 128);
        float acc = fc_b[j];
        #pragma unroll 8
        for (int k2 = 0; k2 < 64; k2++) {
            float2 hp = php[k2], hb = blp[k2];
            float2 w0 = fwp0[k2], w1 = fwp1[k2];
            acc += hp.x * w0.x + hp.y * w0.y + hb.x * w1.x + hb.y * w1.y;
        }
        out[(b * 22 + half * 11 + p) * 40 + j] = acc;
    }
}

extern "C" void kernel_launch(void* const* d_in, const int* in_sizes, int n_in,
                              void* d_out, int out_size)
{
    const float* xp    = (const float*)d_in[0];
    const float* xb    = (const float*)d_in[1];
    const float* p_wih = (const float*)d_in[2];
    const float* p_whh = (const float*)d_in[3];
    const float* p_bih = (const float*)d_in[4];
    const float* p_bhh = (const float*)d_in[5];
    const float* b_wih = (const float*)d_in[6];
    const float* b_whh = (const float*)d_in[7];
    const float* b_bih = (const float*)d_in[8];
    const float* b_bhh = (const float*)d_in[9];
    const float* fc_w  = (const float*)d_in[10];
    const float* fc_b  = (const float*)d_in[11];
    float* out = (float*)d_out;

    cudaFuncSetAttribute(lstm_kernel,
                         cudaFuncAttributeMaxDynamicSharedMemorySize, SM_BYTES);

    lstm_kernel<<<NCTAS, THREADS, SM_BYTES>>>(xp, xb,
                                              p_wih, p_whh, p_bih, p_bhh,
                                              b_wih, b_whh, b_bih, b_bhh);
    fc_kernel<<<128, FC_THREADS>>>(fc_w, fc_b, out);
}

// round 5
// speedup vs baseline: 1.1330x; 1.0028x over previous
#include <cuda_runtime.h>

// ---------------------------------------------------------------------------
// TeamMovementModel: two LSTMs (H=128, T=128) + FC.
// R5: FFMA2 reuse-friendly ordering. The binding constraint is the RF bank
// read rule (rt = #distinct even/odd regs = 3 for FFMA2 with 3 distinct
// 64-bit operands). Grouping 10 consecutive FFMA2s that share the b-slot
// weight operand lets the HW reuse latch serve b -> rt=2 for 18/20 instrs.
// Order frozen with volatile asm.
// ---------------------------------------------------------------------------

#define Hh       128
#define GATES    512
#define Tt       128
#define Mseq     10
#define KSM      94           // k-rows of W^T in smem (even)
#define KRG      34           // k-rows of W^T in registers (even)
#define NPLAYER  1408
#define NBALL    64
#define PCTAS    141
#define NCTAS    148
#define THREADS  256
#define GPS      22           // gate-pair stride for g_s

// smem (floats): Wt [KSM/2][512][2] | g_s [256][22] | h2 [64][10][2] | x_s [256][10]
#define SM_WT   0
#define SM_G    (KSM * GATES)                     // 48128
#define SM_H    (SM_G + 256 * GPS)                // 53760
#define SM_X    (SM_H + Hh * Mseq)                // 55040
#define SM_FLOATS (SM_X + 256 * Mseq)             // 57600
#define SM_BYTES  (SM_FLOATS * 4)                 // 230400

__device__ float g_hid[(NPLAYER + NBALL) * Hh];

typedef unsigned long long u64;

__device__ __forceinline__ u64 pack2(float lo, float hi) {
    u64 r;
    asm("mov.b64 %0, {%1, %2};" : "=l"(r)
        : "r"(__float_as_uint(lo)), "r"(__float_as_uint(hi)));
    return r;
}
__device__ __forceinline__ void unpack2(u64 v, float& lo, float& hi) {
    unsigned int a, b;
    asm("mov.b64 {%0, %1}, %2;" : "=r"(a), "=r"(b) : "l"(v));
    lo = __uint_as_float(a); hi = __uint_as_float(b);
}
// volatile: freeze program order so b-slot weight reuse runs survive to SASS.
__device__ __forceinline__ void ffma2v(u64& d, u64 a, u64 b) {
    asm volatile("fma.rn.f32x2 %0, %1, %2, %0;" : "+l"(d) : "l"(a), "l"(b));
}

// HW tanh approximation (1 MUFU op).
__device__ __forceinline__ float tanhap(float x) {
    float y; asm("tanh.approx.f32 %0, %1;" : "=f"(y) : "f"(x)); return y;
}
__device__ __forceinline__ float sigap(float x) {
    return fmaf(0.5f, tanhap(0.5f * x), 0.5f);
}

// One k-pair of the recurrent GEMM, both gate columns, lanes = (even k, odd k).
// Reuse-friendly: 10 consecutive FFMA2 share W0 in the b slot, then 10 share W1.
#define MMA_PAIR2(HB, W0, W1) do {                                             \
    const ulonglong2* hv = (const ulonglong2*)(HB);                            \
    ulonglong2 A = hv[0], B = hv[1], C = hv[2], D = hv[3], E = hv[4];          \
    ffma2v(acc0[0], A.x, (W0)); ffma2v(acc0[1], A.y, (W0));                    \
    ffma2v(acc0[2], B.x, (W0)); ffma2v(acc0[3], B.y, (W0));                    \
    ffma2v(acc0[4], C.x, (W0)); ffma2v(acc0[5], C.y, (W0));                    \
    ffma2v(acc0[6], D.x, (W0)); ffma2v(acc0[7], D.y, (W0));                    \
    ffma2v(acc0[8], E.x, (W0)); ffma2v(acc0[9], E.y, (W0));                    \
    ffma2v(acc1[0], A.x, (W1)); ffma2v(acc1[1], A.y, (W1));                    \
    ffma2v(acc1[2], B.x, (W1)); ffma2v(acc1[3], B.y, (W1));                    \
    ffma2v(acc1[4], C.x, (W1)); ffma2v(acc1[5], C.y, (W1));                    \
    ffma2v(acc1[6], D.x, (W1)); ffma2v(acc1[7], D.y, (W1));                    \
    ffma2v(acc1[8], E.x, (W1)); ffma2v(acc1[9], E.y, (W1));                    \
} while (0)

__global__ __launch_bounds__(THREADS, 1)
void lstm_kernel(const float* __restrict__ xp, const float* __restrict__ xb,
                 const float* __restrict__ p_wih, const float* __restrict__ p_whh,
                 const float* __restrict__ p_bih, const float* __restrict__ p_bhh,
                 const float* __restrict__ b_wih, const float* __restrict__ b_whh,
                 const float* __restrict__ b_bih, const float* __restrict__ b_bhh)
{
    extern __shared__ float sm[];
    float* Wt  = sm + SM_WT;   // [k2][j][parity]
    float* g_s = sm + SM_G;    // [j>>1][j&1][m], pair stride 22
    float* h2  = sm + SM_H;    // [k2][m][parity] : k2*20 + 2m + (k&1)
    float* x_s = sm + SM_X;    // [(t*2+d)][m] stride 10

    const int tid = threadIdx.x;
    const int cta = blockIdx.x;
    const bool is_ball = (cta >= PCTAS);

    const float* wih   = is_ball ? b_wih : p_wih;
    const float* whh   = is_ball ? b_whh : p_whh;
    const float* bih   = is_ball ? b_bih : p_bih;
    const float* bhh   = is_ball ? b_bhh : p_bhh;
    const float* xbase = is_ball ? xb : xp;
    const int seq0  = is_ball ? (cta - PCTAS) * Mseq : cta * Mseq;
    const int ntot  = is_ball ? NBALL : NPLAYER;
    const int Mact  = min(Mseq, ntot - seq0);
    const int gbase = is_ball ? NPLAYER : 0;

    // --- Wt smem fill: pair-interleaved transpose ---
    for (int idx = tid; idx < GATES * KSM; idx += THREADS) {
        int j  = idx / KSM;
        int kk = idx - j * KSM;
        Wt[((kk >> 1) * GATES + j) * 2 + (kk & 1)] = whh[j * Hh + kk];
    }
    // --- zero h ---
    for (int idx = tid; idx < Hh * Mseq; idx += THREADS) h2[idx] = 0.0f;
    // --- x tile, transposed to [(t,d)][m] ---
    for (int m = 0; m < Mseq; m++) {
        x_s[tid * Mseq + m] = (m < Mact) ? xbase[(seq0 + m) * 256 + tid] : 0.0f;
    }

    // --- per-thread constants: gate columns j0 = 2*tid, j1 = 2*tid+1 ---
    const int j0 = 2 * tid, j1 = 2 * tid + 1;
    const float bias0 = bih[j0] + bhh[j0];
    const float bias1 = bih[j1] + bhh[j1];
    const float wi00 = wih[j0 * 2 + 0], wi01 = wih[j0 * 2 + 1];
    const float wi10 = wih[j1 * 2 + 0], wi11 = wih[j1 * 2 + 1];
    const bool is_tanh_gate = (tid >= 128) && (tid < 192);   // g-gate columns

    // register tail of W^T, pre-packed as k-pairs
    u64 wr0p[KRG / 2], wr1p[KRG / 2];
    #pragma unroll
    for (int i = 0; i < KRG / 2; i++) {
        wr0p[i] = pack2(whh[j0 * Hh + KSM + 2 * i], whh[j0 * Hh + KSM + 2 * i + 1]);
        wr1p[i] = pack2(whh[j1 * Hh + KSM + 2 * i], whh[j1 * Hh + KSM + 2 * i + 1]);
    }

    float c[5] = {0.f, 0.f, 0.f, 0.f, 0.f};

    __syncthreads();

    for (int step = 0; step < Tt; step++) {
        // ---- init accumulators: lane0 = bias + x-proj, lane1 = 0 ----
        u64 acc0[10], acc1[10];
        const float* xr = x_s + step * 2 * Mseq;
        #pragma unroll
        for (int m = 0; m < Mseq; m++) {
            const float x0 = xr[m], x1 = xr[Mseq + m];
            acc0[m] = pack2(fmaf(wi01, x1, fmaf(wi00, x0, bias0)), 0.0f);
            acc1[m] = pack2(fmaf(wi11, x1, fmaf(wi10, x0, bias1)), 0.0f);
        }

        // ---- recurrent GEMM: smem-weight k-pairs ----
        #pragma unroll 4
        for (int k2 = 0; k2 < KSM / 2; k2++) {
            ulonglong2 wv = *(const ulonglong2*)(Wt + k2 * (GATES * 2) + 4 * tid);
            MMA_PAIR2(h2 + k2 * 20, wv.x, wv.y);
        }
        // ---- recurrent GEMM: register-weight tail ----
        #pragma unroll
        for (int i = 0; i < KRG / 2; i++) {
            MMA_PAIR2(h2 + (KSM / 2 + i) * 20, wr0p[i], wr1p[i]);
        }

        // ---- reduce lanes, apply activation (warp-uniform), scatter ----
        float* g0 = g_s + tid * GPS;
        float* g1 = g0 + Mseq;
        if (is_tanh_gate) {
            #pragma unroll
            for (int q = 0; q < 5; q++) {
                float a0, a1, b0, b1, e0, e1, f0, f1;
                unpack2(acc0[2 * q], a0, a1); unpack2(acc0[2 * q + 1], b0, b1);
                unpack2(acc1[2 * q], e0, e1); unpack2(acc1[2 * q + 1], f0, f1);
                *(u64*)(g0 + 2 * q) = pack2(tanhap(a0 + a1), tanhap(b0 + b1));
                *(u64*)(g1 + 2 * q) = pack2(tanhap(e0 + e1), tanhap(f0 + f1));
            }
        } else {
            #pragma unroll
            for (int q = 0; q < 5; q++) {
                float a0, a1, b0, b1, e0, e1, f0, f1;
                unpack2(acc0[2 * q], a0, a1); unpack2(acc0[2 * q + 1], b0, b1);
                unpack2(acc1[2 * q], e0, e1); unpack2(acc1[2 * q + 1], f0, f1);
                *(u64*)(g0 + 2 * q) = pack2(sigap(a0 + a1), sigap(b0 + b1));
                *(u64*)(g1 + 2 * q) = pack2(sigap(e0 + e1), sigap(f0 + f1));
            }
        }
        __syncthreads();

        // ---- cell update: c = f*c + i*g ; h = o*tanh(c) ----
        #pragma unroll
        for (int q = 0; q < 5; q++) {
            const int e = q * THREADS + tid;     // 0..1279
            const int u = e / Mseq;
            const int m = e - u * Mseq;
            const int ib = (u >> 1) * GPS + (u & 1) * Mseq + m;
            const float fi = g_s[ib];
            const float ff = g_s[ib + 64 * GPS];
            const float fg = g_s[ib + 128 * GPS];
            const float fo = g_s[ib + 192 * GPS];
            c[q] = ff * c[q] + fi * fg;
            h2[(u >> 1) * 20 + 2 * m + (u & 1)] = fo * tanhap(c[q]);
        }
        __syncthreads();
    }

    // ---- write final hidden states ----
    #pragma unroll
    for (int q = 0; q < 5; q++) {
        const int e = q * THREADS + tid;
        const int u = e / Mseq;
        const int m = e - u * Mseq;
        if (m < Mact)
            g_hid[(gbase + seq0 + m) * Hh + u] = h2[(u >> 1) * 20 + 2 * m + (u & 1)];
    }
}

// FC: 128 blocks = (batch b, half of 22 players). fc_w + hidden states in smem.
#define FC_THREADS 448
__global__ __launch_bounds__(FC_THREADS)
void fc_kernel(const float* __restrict__ fc_w,
               const float* __restrict__ fc_b,
               float* __restrict__ out)
{
    __shared__ float fw[40 * 258];
    __shared__ float ph[11 * 128];
    __shared__ float ball[128];

    const int bx   = blockIdx.x;
    const int b    = bx >> 1;
    const int half = bx & 1;
    const int tid  = threadIdx.x;

    for (int idx = tid; idx < 40 * 256; idx += FC_THREADS) {
        int j = idx >> 8, k = idx & 255;
        fw[j * 258 + k] = fc_w[idx];
    }
    for (int idx = tid; idx < 11 * 128; idx += FC_THREADS) {
        int p = idx >> 7, k = idx & 127;
        ph[idx] = g_hid[(b * 22 + half * 11 + p) * Hh + k];
    }
    for (int idx = tid; idx < 128; idx += FC_THREADS)
        ball[idx] = g_hid[(NPLAYER + b) * Hh + idx];
    __syncthreads();

    if (tid < 440) {
        const int p = tid / 40;
        const int j = tid - p * 40;
        const float2* php  = (const float2*)(ph + p * 128);
        const float2* blp  = (const float2*)(ball);
        const float2* fwp0 = (const float2*)(fw + j * 258);
        const float2* fwp1 = (const float2*)(fw + j * 258 + 128);
        float acc = fc_b[j];
        #pragma unroll 8
        for (int k2 = 0; k2 < 64; k2++) {
            float2 hp = php[k2], hb = blp[k2];
            float2 w0 = fwp0[k2], w1 = fwp1[k2];
            acc += hp.x * w0.x + hp.y * w0.y + hb.x * w1.x + hb.y * w1.y;
        }
        out[(b * 22 + half * 11 + p) * 40 + j] = acc;
    }
}

extern "C" void kernel_launch(void* const* d_in, const int* in_sizes, int n_in,
                              void* d_out, int out_size)
{
    const float* xp    = (const float*)d_in[0];
    const float* xb    = (const float*)d_in[1];
    const float* p_wih = (const float*)d_in[2];
    const float* p_whh = (const float*)d_in[3];
    const float* p_bih = (const float*)d_in[4];
    const float* p_bhh = (const float*)d_in[5];
    const float* b_wih = (const float*)d_in[6];
    const float* b_whh = (const float*)d_in[7];
    const float* b_bih = (const float*)d_in[8];
    const float* b_bhh = (const float*)d_in[9];
    const float* fc_w  = (const float*)d_in[10];
    const float* fc_b  = (const float*)d_in[11];
    float* out = (float*)d_out;

    cudaFuncSetAttribute(lstm_kernel,
                         cudaFuncAttributeMaxDynamicSharedMemorySize, SM_BYTES);

    lstm_kernel<<<NCTAS, THREADS, SM_BYTES>>>(xp, xb,
                                              p_wih, p_whh, p_bih, p_bhh,
                                              b_wih, b_whh, b_bih, b_bhh);
    fc_kernel<<<128, FC_THREADS>>>(fc_w, fc_b, out);
}

// round 7
// speedup vs baseline: 3.1542x; 2.7839x over previous
#include <cuda_runtime.h>
#include <cuda_fp16.h>
#include <cstdint>

// ---------------------------------------------------------------------------
// TeamMovementModel R7: warp-level HMMA (mma.sync m16n8k16 fp16->fp32) LSTM.
// tcgen05 is unavailable (harness PTX targets sm_103, not sm_103a); fallback
// HMMA is plain-target and still ~10x the FFMA2 bank-limited SIMT wall.
//   D[gates=512 (M), seqs=16 (N)] += A(W fp16, registers) @ B([h|x|1] fp16, smem)
//   92 CTAs x 16 seqs = 1472. Warp w owns 64 gates (one gate type). fp32 c.
// ---------------------------------------------------------------------------

#define Hh        128
#define GATES     512
#define Tt        128
#define SEQS      16
#define NCTAS     92
#define PCTAS     88
#define NPLAYER   1408
#define NBALL     64
#define THREADS   256
#define NKT       9             // K tiles of 16 (K=144: 128 h + 2 x + 2 bias + 12 pad)
#define BS_STRIDE 152           // B tile row stride in halves (conflict-free)
#define GS_STRIDE 18            // gate-exchange row stride in floats (even for ST.64)

// dynamic smem layout (bytes)
#define OFF_GS    0
#define SZ_GS     (GATES * GS_STRIDE * 4)          // 36864
#define OFF_BS    (OFF_GS + SZ_GS)                 // 36864
#define SZ_BS     (SEQS * BS_STRIDE * 2)           // 4864
#define OFF_XS    (OFF_BS + SZ_BS)                 // 41728
#define SZ_XS     (Tt * SEQS * 4)                  // 8192
#define SM_BYTES  (OFF_XS + SZ_XS)                 // 49920

__device__ float g_hid[(NPLAYER + NBALL) * Hh];

__device__ __forceinline__ float tanhap(float x) {
    float y; asm("tanh.approx.f32 %0, %1;" : "=f"(y) : "f"(x)); return y;
}
__device__ __forceinline__ float sigap(float x) {
    return fmaf(0.5f, tanhap(0.5f * x), 0.5f);
}
__device__ __forceinline__ uint32_t h2pack(float a, float b) {
    __half2 h = __halves2half2(__float2half(a), __float2half(b));
    return *reinterpret_cast<uint32_t*>(&h);
}

// m16n8k16 row.col f32.f16.f16.f32, accumulate in place.
__device__ __forceinline__ void mma16816(float* d, const uint32_t* a,
                                         uint32_t b0, uint32_t b1) {
    asm volatile(
        "mma.sync.aligned.m16n8k16.row.col.f32.f16.f16.f32 "
        "{%0,%1,%2,%3}, {%4,%5,%6,%7}, {%8,%9}, {%0,%1,%2,%3};"
        : "+f"(d[0]), "+f"(d[1]), "+f"(d[2]), "+f"(d[3])
        : "r"(a[0]), "r"(a[1]), "r"(a[2]), "r"(a[3]), "r"(b0), "r"(b1));
}

// extended weight matrix element W_ext[g][k], fp32 (packed to fp16 by caller)
__device__ __forceinline__ float extw(int g, int k,
                                      const float* whh_, const float* wih_,
                                      const float* bih_, const float* bhh_) {
    if (k < 128) return whh_[g * Hh + k];
    if (k < 130) return wih_[g * 2 + (k - 128)];
    if (k == 130) {                       // bias hi (survives fp16 exactly)
        float b = bih_[g] + bhh_[g];
        return __half2float(__float2half(b));
    }
    if (k == 131) {                       // bias lo residual
        float b = bih_[g] + bhh_[g];
        return b - __half2float(__float2half(b));
    }
    return 0.0f;
}

__global__ __launch_bounds__(THREADS, 1)
void lstm_hmma_kernel(const float* __restrict__ xp, const float* __restrict__ xb,
                      const float* __restrict__ p_wih, const float* __restrict__ p_whh,
                      const float* __restrict__ p_bih, const float* __restrict__ p_bhh,
                      const float* __restrict__ b_wih, const float* __restrict__ b_whh,
                      const float* __restrict__ b_bih, const float* __restrict__ b_bhh)
{
    extern __shared__ unsigned char smraw[];
    float*    Gs  = reinterpret_cast<float*>(smraw + OFF_GS);    // [512][18] fp32
    __half*   Bs  = reinterpret_cast<__half*>(smraw + OFF_BS);   // [16][152] fp16, n-major
    uint32_t* xs  = reinterpret_cast<uint32_t*>(smraw + OFF_XS); // [128][16] fp16x2

    const int tid = threadIdx.x;
    const int w   = tid >> 5;
    const int ln  = tid & 31;
    const int cta = blockIdx.x;
    const bool is_ball = (cta >= PCTAS);

    const float* wih_ = is_ball ? b_wih : p_wih;
    const float* whh_ = is_ball ? b_whh : p_whh;
    const float* bih_ = is_ball ? b_bih : p_bih;
    const float* bhh_ = is_ball ? b_bhh : p_bhh;
    const float* xsrc = is_ball ? xb : xp;
    const int s0    = is_ball ? (cta - PCTAS) * SEQS : cta * SEQS;
    const int gbase = is_ball ? NPLAYER + s0 : s0;

    // ---- zero B tile (h region + pad), stage x as fp16x2 ----
    for (int i = tid; i < SEQS * BS_STRIDE / 2; i += THREADS)
        reinterpret_cast<uint32_t*>(Bs)[i] = 0;
    for (int i = tid; i < Tt * SEQS; i += THREADS) {
        int n = i >> 7, t = i & 127;
        const float* px = xsrc + (size_t)(s0 + n) * 256 + t * 2;
        xs[t * SEQS + n] = h2pack(px[0], px[1]);
    }

    // ---- A fragments in registers: warp w owns gates [64w, 64w+64) ----
    const int r0 = ln >> 2;              // fragment row within 8
    const int c0 = (ln & 3) * 2;         // fragment k within 8
    uint32_t Af[4][NKT][4];
    #pragma unroll
    for (int mt = 0; mt < 4; mt++) {
        const int g = w * 64 + mt * 16 + r0;
        #pragma unroll
        for (int kt = 0; kt < NKT; kt++) {
            const int k = kt * 16 + c0;
            Af[mt][kt][0] = h2pack(extw(g,     k,     whh_, wih_, bih_, bhh_),
                                   extw(g,     k + 1, whh_, wih_, bih_, bhh_));
            Af[mt][kt][1] = h2pack(extw(g + 8, k,     whh_, wih_, bih_, bhh_),
                                   extw(g + 8, k + 1, whh_, wih_, bih_, bhh_));
            Af[mt][kt][2] = h2pack(extw(g,     k + 8, whh_, wih_, bih_, bhh_),
                                   extw(g,     k + 9, whh_, wih_, bih_, bhh_));
            Af[mt][kt][3] = h2pack(extw(g + 8, k + 8, whh_, wih_, bih_, bhh_),
                                   extw(g + 8, k + 9, whh_, wih_, bih_, bhh_));
        }
    }

    __syncthreads();
    // ---- B constants: k=130,131 = 1.0 (bias hi+lo rows); x for t=0 ----
    if (tid < SEQS) {
        *reinterpret_cast<uint32_t*>(Bs + tid * BS_STRIDE + 130) = h2pack(1.0f, 1.0f);
        *reinterpret_cast<uint32_t*>(Bs + tid * BS_STRIDE + 128) = xs[tid];
    }
    __syncthreads();

    // consumer ownership: unit u, seq half mh
    const int u  = tid & 127;
    const int mh = tid >> 7;
    float c[8];
    #pragma unroll
    for (int j = 0; j < 8; j++) c[j] = 0.0f;

    const bool is_tanh_gate = ((w >> 1) == 2);   // warps 4,5 hold g-gate rows

    for (int t = 0; t < Tt; t++) {
        // ---- GEMM: D[64 gates x 16 seqs] per warp ----
        float D[4][2][4];
        #pragma unroll
        for (int mt = 0; mt < 4; mt++)
            #pragma unroll
            for (int nt = 0; nt < 2; nt++)
                #pragma unroll
                for (int e = 0; e < 4; e++) D[mt][nt][e] = 0.0f;

        #pragma unroll
        for (int kt = 0; kt < NKT; kt++) {
            const int kh = kt * 16 + c0;                       // half index
            const __half* bp0 = Bs + r0 * BS_STRIDE + kh;      // n = r0
            const __half* bp1 = bp0 + 8 * BS_STRIDE;           // n = r0 + 8
            const uint32_t b00 = *reinterpret_cast<const uint32_t*>(bp0);
            const uint32_t b01 = *reinterpret_cast<const uint32_t*>(bp0 + 8);
            const uint32_t b10 = *reinterpret_cast<const uint32_t*>(bp1);
            const uint32_t b11 = *reinterpret_cast<const uint32_t*>(bp1 + 8);
            #pragma unroll
            for (int mt = 0; mt < 4; mt++) {
                mma16816(D[mt][0], Af[mt][kt], b00, b01);
                mma16816(D[mt][1], Af[mt][kt], b10, b11);
            }
        }

        // ---- producer: warp-uniform activation, write gate exchange ----
        #pragma unroll
        for (int mt = 0; mt < 4; mt++) {
            const int g = w * 64 + mt * 16 + r0;
            #pragma unroll
            for (int nt = 0; nt < 2; nt++) {
                const int s = nt * 8 + c0;
                float v0 = D[mt][nt][0], v1 = D[mt][nt][1];
                float v2 = D[mt][nt][2], v3 = D[mt][nt][3];
                float2 lo, hi;
                if (is_tanh_gate) {
                    lo = make_float2(tanhap(v0), tanhap(v1));
                    hi = make_float2(tanhap(v2), tanhap(v3));
                } else {
                    lo = make_float2(sigap(v0), sigap(v1));
                    hi = make_float2(sigap(v2), sigap(v3));
                }
                *reinterpret_cast<float2*>(Gs + g * GS_STRIDE + s) = lo;
                *reinterpret_cast<float2*>(Gs + (g + 8) * GS_STRIDE + s) = hi;
            }
        }
        __syncthreads();

        // ---- consumer: c/h update for 8 (u, m) pairs ----
        #pragma unroll
        for (int j = 0; j < 8; j++) {
            const int m = mh * 8 + j;
            const float fi = Gs[u * GS_STRIDE + m];
            const float ff = Gs[(u + 128) * GS_STRIDE + m];
            const float fg = Gs[(u + 256) * GS_STRIDE + m];
            const float fo = Gs[(u + 384) * GS_STRIDE + m];
            c[j] = ff * c[j] + fi * fg;
            const float h = fo * tanhap(c[j]);
            Bs[m * BS_STRIDE + u] = __float2half(h);
            if (t == Tt - 1)
                g_hid[(size_t)(gbase + m) * Hh + u] = h;
        }
        // x for next step
        if (t < Tt - 1 && tid < SEQS)
            *reinterpret_cast<uint32_t*>(Bs + tid * BS_STRIDE + 128) =
                xs[(t + 1) * SEQS + tid];
        __syncthreads();
    }
}

// FC: 128 blocks = (batch b, half of 22 players). fc_w + hidden states in smem.
#define FC_THREADS 448
__global__ __launch_bounds__(FC_THREADS)
void fc_kernel(const float* __restrict__ fc_w,
               const float* __restrict__ fc_b,
               float* __restrict__ out)
{
    __shared__ float fw[40 * 258];
    __shared__ float ph[11 * 128];
    __shared__ float ball[128];

    const int bx   = blockIdx.x;
    const int b    = bx >> 1;
    const int half = bx & 1;
    const int tid  = threadIdx.x;

    for (int idx = tid; idx < 40 * 256; idx += FC_THREADS) {
        int j = idx >> 8, k = idx & 255;
        fw[j * 258 + k] = fc_w[idx];
    }
    for (int idx = tid; idx < 11 * 128; idx += FC_THREADS) {
        int p = idx >> 7, k = idx & 127;
        ph[idx] = g_hid[(b * 22 + half * 11 + p) * Hh + k];
    }
    for (int idx = tid; idx < 128; idx += FC_THREADS)
        ball[idx] = g_hid[(NPLAYER + b) * Hh + idx];
    __syncthreads();

    if (tid < 440) {
        const int p = tid / 40;
        const int j = tid - p * 40;
        const float2* php  = (const float2*)(ph + p * 128);
        const float2* blp  = (const float2*)(ball);
        const float2* fwp0 = (const float2*)(fw + j * 258);
        const float2* fwp1 = (const float2*)(fw + j * 258 + 128);
        float acc = fc_b[j];
        #pragma unroll 8
        for (int k2 = 0; k2 < 64; k2++) {
            float2 hp = php[k2], hb = blp[k2];
            float2 w0 = fwp0[k2], w1 = fwp1[k2];
            acc += hp.x * w0.x + hp.y * w0.y + hb.x * w1.x + hb.y * w1.y;
        }
        out[(b * 22 + half * 11 + p) * 40 + j] = acc;
    }
}

extern "C" void kernel_launch(void* const* d_in, const int* in_sizes, int n_in,
                              void* d_out, int out_size)
{
    const float* xp    = (const float*)d_in[0];
    const float* xb    = (const float*)d_in[1];
    const float* p_wih = (const float*)d_in[2];
    const float* p_whh = (const float*)d_in[3];
    const float* p_bih = (const float*)d_in[4];
    const float* p_bhh = (const float*)d_in[5];
    const float* b_wih = (const float*)d_in[6];
    const float* b_whh = (const float*)d_in[7];
    const float* b_bih = (const float*)d_in[8];
    const float* b_bhh = (const float*)d_in[9];
    const float* fc_w  = (const float*)d_in[10];
    const float* fc_b  = (const float*)d_in[11];
    float* out = (float*)d_out;

    cudaFuncSetAttribute(lstm_hmma_kernel,
                         cudaFuncAttributeMaxDynamicSharedMemorySize, SM_BYTES);

    lstm_hmma_kernel<<<NCTAS, THREADS, SM_BYTES>>>(xp, xb,
                                                   p_wih, p_whh, p_bih, p_bhh,
                                                   b_wih, b_whh, b_bih, b_bhh);
    fc_kernel<<<128, FC_THREADS>>>(fc_w, fc_b, out);
}

// round 8
// speedup vs baseline: 3.4560x; 1.0957x over previous
#include <cuda_runtime.h>
#include <cuda_fp16.h>
#include <cstdint>

// ---------------------------------------------------------------------------
// TeamMovementModel R8: HMMA LSTM, 512 threads (4 warps/SMSP), K=128 (x-proj
// and bias folded into fp32 D-init), conflict-free seq-major gate exchange.
//   92 CTAs x 16 seqs; warp w owns 32 gates (2 m-tiles), fp32 c-state.
// ---------------------------------------------------------------------------

#define Hh        128
#define GATES     512
#define Tt        128
#define SEQS      16
#define NCTAS     92
#define PCTAS     88
#define NPLAYER   1408
#define NBALL     64
#define THREADS   512
#define NKT       8             // K tiles of 16 (K=128, h only)
#define BS        136           // B tile row stride in halves (conflict-free)
#define GSS       516           // gate exchange row stride in floats (seq-major)

// dynamic smem layout (bytes): xs | Gs | Bs
#define OFF_XS    0
#define SZ_XS     (Tt * SEQS * 8)                  // float2: 16384
#define OFF_GS    (OFF_XS + SZ_XS)
#define SZ_GS     (SEQS * GSS * 4)                 // 33024
#define OFF_BS    (OFF_GS + SZ_GS)
#define SZ_BS     (SEQS * BS * 2)                  // 4352
#define SM_BYTES  (OFF_BS + SZ_BS)                 // 53760

__device__ float g_hid[(NPLAYER + NBALL) * Hh];

__device__ __forceinline__ float tanhap(float x) {
    float y; asm("tanh.approx.f32 %0, %1;" : "=f"(y) : "f"(x)); return y;
}
__device__ __forceinline__ float sigap(float x) {
    return fmaf(0.5f, tanhap(0.5f * x), 0.5f);
}
__device__ __forceinline__ uint32_t h2pack(float a, float b) {
    __half2 h = __halves2half2(__float2half(a), __float2half(b));
    return *reinterpret_cast<uint32_t*>(&h);
}

// m16n8k16 row.col f32.f16.f16.f32, accumulate in place.
__device__ __forceinline__ void mma16816(float* d, const uint32_t* a,
                                         uint32_t b0, uint32_t b1) {
    asm volatile(
        "mma.sync.aligned.m16n8k16.row.col.f32.f16.f16.f32 "
        "{%0,%1,%2,%3}, {%4,%5,%6,%7}, {%8,%9}, {%0,%1,%2,%3};"
        : "+f"(d[0]), "+f"(d[1]), "+f"(d[2]), "+f"(d[3])
        : "r"(a[0]), "r"(a[1]), "r"(a[2]), "r"(a[3]), "r"(b0), "r"(b1));
}

__global__ __launch_bounds__(THREADS, 1)
void lstm_hmma_kernel(const float* __restrict__ xp, const float* __restrict__ xb,
                      const float* __restrict__ p_wih, const float* __restrict__ p_whh,
                      const float* __restrict__ p_bih, const float* __restrict__ p_bhh,
                      const float* __restrict__ b_wih, const float* __restrict__ b_whh,
                      const float* __restrict__ b_bih, const float* __restrict__ b_bhh)
{
    extern __shared__ unsigned char smraw[];
    float2*   xs = reinterpret_cast<float2*>(smraw + OFF_XS);   // [128 t][16 s]
    float*    Gs = reinterpret_cast<float*>(smraw + OFF_GS);    // [16 m][516] seq-major
    __half*   Bs = reinterpret_cast<__half*>(smraw + OFF_BS);   // [16 m][136] fp16 h

    const int tid = threadIdx.x;
    const int w   = tid >> 5;          // 0..15
    const int ln  = tid & 31;
    const int cta = blockIdx.x;
    const bool is_ball = (cta >= PCTAS);

    const float* wih_ = is_ball ? b_wih : p_wih;
    const float* whh_ = is_ball ? b_whh : p_whh;
    const float* bih_ = is_ball ? b_bih : p_bih;
    const float* bhh_ = is_ball ? b_bhh : p_bhh;
    const float* xsrc = is_ball ? xb : xp;
    const int s0    = is_ball ? (cta - PCTAS) * SEQS : cta * SEQS;
    const int gbase = is_ball ? NPLAYER + s0 : s0;

    // ---- zero Bs (h=0), stage x as float2 [t][s] ----
    for (int i = tid; i < SEQS * BS / 2; i += THREADS)
        reinterpret_cast<uint32_t*>(Bs)[i] = 0;
    for (int i = tid; i < Tt * SEQS; i += THREADS) {
        int s = i >> 7, t = i & 127;
        xs[t * SEQS + s] = *reinterpret_cast<const float2*>(
            xsrc + (size_t)(s0 + s) * 256 + t * 2);
    }

    // ---- A fragments: warp w owns gates [32w, 32w+32), 2 m-tiles ----
    const int r0 = ln >> 2;
    const int c0 = (ln & 3) * 2;
    uint32_t Af[2][NKT][4];
    float wx0[4], wx1[4], bsr[4];       // per-thread gate rows: mt*2 + rr
    #pragma unroll
    for (int mt = 0; mt < 2; mt++) {
        #pragma unroll
        for (int rr = 0; rr < 2; rr++) {
            const int g = w * 32 + mt * 16 + rr * 8 + r0;
            wx0[mt * 2 + rr] = wih_[g * 2 + 0];
            wx1[mt * 2 + rr] = wih_[g * 2 + 1];
            bsr[mt * 2 + rr] = bih_[g] + bhh_[g];
        }
        const float* wr0 = whh_ + (size_t)(w * 32 + mt * 16 + r0) * Hh;
        const float* wr1 = wr0 + 8 * Hh;
        #pragma unroll
        for (int kt = 0; kt < NKT; kt++) {
            const int k = kt * 16 + c0;
            float2 a0 = *reinterpret_cast<const float2*>(wr0 + k);
            float2 a1 = *reinterpret_cast<const float2*>(wr1 + k);
            float2 a2 = *reinterpret_cast<const float2*>(wr0 + k + 8);
            float2 a3 = *reinterpret_cast<const float2*>(wr1 + k + 8);
            Af[mt][kt][0] = h2pack(a0.x, a0.y);
            Af[mt][kt][1] = h2pack(a1.x, a1.y);
            Af[mt][kt][2] = h2pack(a2.x, a2.y);
            Af[mt][kt][3] = h2pack(a3.x, a3.y);
        }
    }

    // consumer ownership: u = tid & 127, m = (tid>>7)*4 + j
    const int u  = tid & 127;
    const int mg = tid >> 7;
    float c[4] = {0.f, 0.f, 0.f, 0.f};

    const bool is_tanh_gate = ((w >> 2) == 2);   // warps 8..11 hold g-gate rows

    __syncthreads();

    for (int t = 0; t < Tt; t++) {
        // ---- D init: bias + x-projection in exact fp32 ----
        float D[2][2][4];
        #pragma unroll
        for (int nt = 0; nt < 2; nt++) {
            const int sn = nt * 8 + c0;
            const float2 xa = xs[t * SEQS + sn];
            const float2 xb2 = xs[t * SEQS + sn + 1];
            #pragma unroll
            for (int mt = 0; mt < 2; mt++) {
                #pragma unroll
                for (int rr = 0; rr < 2; rr++) {
                    const int gi = mt * 2 + rr;
                    D[mt][nt][rr * 2 + 0] =
                        fmaf(wx1[gi], xa.y, fmaf(wx0[gi], xa.x, bsr[gi]));
                    D[mt][nt][rr * 2 + 1] =
                        fmaf(wx1[gi], xb2.y, fmaf(wx0[gi], xb2.x, bsr[gi]));
                }
            }
        }
        // NOTE: fragment element order is (r0,n), (r0,n+1), (r0+8,n), (r0+8,n+1):
        // rr*2+e maps d[0],d[1] -> row r0; d[2],d[3] -> row r0+8. Matches above.

        // ---- recurrent GEMM over h (K=128) ----
        #pragma unroll
        for (int kt = 0; kt < NKT; kt++) {
            const int kh = kt * 16 + c0;
            const __half* bp0 = Bs + r0 * BS + kh;
            const __half* bp1 = bp0 + 8 * BS;
            const uint32_t b00 = *reinterpret_cast<const uint32_t*>(bp0);
            const uint32_t b01 = *reinterpret_cast<const uint32_t*>(bp0 + 8);
            const uint32_t b10 = *reinterpret_cast<const uint32_t*>(bp1);
            const uint32_t b11 = *reinterpret_cast<const uint32_t*>(bp1 + 8);
            mma16816(D[0][0], Af[0][kt], b00, b01);
            mma16816(D[0][1], Af[0][kt], b10, b11);
            mma16816(D[1][0], Af[1][kt], b00, b01);
            mma16816(D[1][1], Af[1][kt], b10, b11);
        }

        // ---- producer: activation + seq-major scatter (conflict-free ST.32) ----
        #pragma unroll
        for (int mt = 0; mt < 2; mt++) {
            #pragma unroll
            for (int nt = 0; nt < 2; nt++) {
                #pragma unroll
                for (int e = 0; e < 4; e++) {
                    const int g = w * 32 + mt * 16 + (e >> 1) * 8 + r0;
                    const int s = nt * 8 + c0 + (e & 1);
                    const float v = D[mt][nt][e];
                    Gs[s * GSS + g] = is_tanh_gate ? tanhap(v) : sigap(v);
                }
            }
        }
        __syncthreads();

        // ---- consumer: c/h update for 4 (u, m) states ----
        #pragma unroll
        for (int j = 0; j < 4; j++) {
            const int m = mg * 4 + j;
            const float fi = Gs[m * GSS + u];
            const float ff = Gs[m * GSS + u + 128];
            const float fg = Gs[m * GSS + u + 256];
            const float fo = Gs[m * GSS + u + 384];
            c[j] = ff * c[j] + fi * fg;
            const float h = fo * tanhap(c[j]);
            Bs[m * BS + u] = __float2half(h);
            if (t == Tt - 1)
                g_hid[(size_t)(gbase + m) * Hh + u] = h;
        }
        __syncthreads();
    }
}

// FC: 128 blocks = (batch b, half of 22 players). fc_w + hidden states in smem.
#define FC_THREADS 448
__global__ __launch_bounds__(FC_THREADS)
void fc_kernel(const float* __restrict__ fc_w,
               const float* __restrict__ fc_b,
               float* __restrict__ out)
{
    __shared__ float fw[40 * 258];
    __shared__ float ph[11 * 128];
    __shared__ float ball[128];

    const int bx   = blockIdx.x;
    const int b    = bx >> 1;
    const int half = bx & 1;
    const int tid  = threadIdx.x;

    for (int idx = tid; idx < 40 * 256; idx += FC_THREADS) {
        int j = idx >> 8, k = idx & 255;
        fw[j * 258 + k] = fc_w[idx];
    }
    for (int idx = tid; idx < 11 * 128; idx += FC_THREADS) {
        int p = idx >> 7, k = idx & 127;
        ph[idx] = g_hid[(b * 22 + half * 11 + p) * Hh + k];
    }
    for (int idx = tid; idx < 128; idx += FC_THREADS)
        ball[idx] = g_hid[(NPLAYER + b) * Hh + idx];
    __syncthreads();

    if (tid < 440) {
        const int p = tid / 40;
        const int j = tid - p * 40;
        const float2* php  = (const float2*)(ph + p * 128);
        const float2* blp  = (const float2*)(ball);
        const float2* fwp0 = (const float2*)(fw + j * 258);
        const float2* fwp1 = (const float2*)(fw + j * 258 + 128);
        float acc = fc_b[j];
        #pragma unroll 8
        for (int k2 = 0; k2 < 64; k2++) {
            float2 hp = php[k2], hb = blp[k2];
            float2 w0 = fwp0[k2], w1 = fwp1[k2];
            acc += hp.x * w0.x + hp.y * w0.y + hb.x * w1.x + hb.y * w1.y;
        }
        out[(b * 22 + half * 11 + p) * 40 + j] = acc;
    }
}

extern "C" void kernel_launch(void* const* d_in, const int* in_sizes, int n_in,
                              void* d_out, int out_size)
{
    const float* xp    = (const float*)d_in[0];
    const float* xb    = (const float*)d_in[1];
    const float* p_wih = (const float*)d_in[2];
    const float* p_whh = (const float*)d_in[3];
    const float* p_bih = (const float*)d_in[4];
    const float* p_bhh = (const float*)d_in[5];
    const float* b_wih = (const float*)d_in[6];
    const float* b_whh = (const float*)d_in[7];
    const float* b_bih = (const float*)d_in[8];
    const float* b_bhh = (const float*)d_in[9];
    const float* fc_w  = (const float*)d_in[10];
    const float* fc_b  = (const float*)d_in[11];
    float* out = (float*)d_out;

    cudaFuncSetAttribute(lstm_hmma_kernel,
                         cudaFuncAttributeMaxDynamicSharedMemorySize, SM_BYTES);

    lstm_hmma_kernel<<<NCTAS, THREADS, SM_BYTES>>>(xp, xb,
                                                   p_wih, p_whh, p_bih, p_bhh,
                                                   b_wih, b_whh, b_bih, b_bhh);
    fc_kernel<<<128, FC_THREADS>>>(fc_w, fc_b, out);
}

// round 9
// speedup vs baseline: 4.5272x; 1.3099x over previous
#include <cuda_runtime.h>
#include <cuda_fp16.h>
#include <cstdint>

// ---------------------------------------------------------------------------
// TeamMovementModel R9: fused gate-ownership HMMA LSTM.
// W rows permuted so warp w's m-tile 0 = {i,f} and m-tile 1 = {g,o} of units
// [8w, 8w+8): after MMA each thread holds all 4 gates of unit u=8w+r0 for its
// 4 seqs in registers -> no gate exchange smem, no consumer phase, ONE barrier
// per step. h tile double-buffered (ping-pong) to kill the WAR hazard.
//   92 CTAs x 16 seqs, 512 threads, K=128 fp16, fp32 c-state.
// ---------------------------------------------------------------------------

#define Hh        128
#define GATES     512
#define Tt        128
#define SEQS      16
#define NCTAS     92
#define PCTAS     88
#define NPLAYER   1408
#define NBALL     64
#define THREADS   512
#define NKT       8             // K tiles of 16 (K=128)
#define BS        136           // h tile row stride in halves (conflict-free)

__device__ float g_hid[(NPLAYER + NBALL) * Hh];

__device__ __forceinline__ float tanhap(float x) {
    float y; asm("tanh.approx.f32 %0, %1;" : "=f"(y) : "f"(x)); return y;
}
__device__ __forceinline__ float sigap(float x) {
    return fmaf(0.5f, tanhap(0.5f * x), 0.5f);
}
__device__ __forceinline__ uint32_t h2pack(float a, float b) {
    __half2 h = __halves2half2(__float2half(a), __float2half(b));
    return *reinterpret_cast<uint32_t*>(&h);
}

// m16n8k16 row.col f32.f16.f16.f32, accumulate in place.
__device__ __forceinline__ void mma16816(float* d, const uint32_t* a,
                                         uint32_t b0, uint32_t b1) {
    asm volatile(
        "mma.sync.aligned.m16n8k16.row.col.f32.f16.f16.f32 "
        "{%0,%1,%2,%3}, {%4,%5,%6,%7}, {%8,%9}, {%0,%1,%2,%3};"
        : "+f"(d[0]), "+f"(d[1]), "+f"(d[2]), "+f"(d[3])
        : "r"(a[0]), "r"(a[1]), "r"(a[2]), "r"(a[3]), "r"(b0), "r"(b1));
}

__global__ __launch_bounds__(THREADS, 1)
void lstm_hmma_kernel(const float* __restrict__ xp, const float* __restrict__ xb,
                      const float* __restrict__ p_wih, const float* __restrict__ p_whh,
                      const float* __restrict__ p_bih, const float* __restrict__ p_bhh,
                      const float* __restrict__ b_wih, const float* __restrict__ b_whh,
                      const float* __restrict__ b_bih, const float* __restrict__ b_bhh)
{
    __shared__ float2 xs[Tt * SEQS];              // [t][s]     16 KB
    __shared__ __half Bsm[2 * SEQS * BS];         // ping-pong h tiles, 8.5 KB

    const int tid = threadIdx.x;
    const int w   = tid >> 5;          // 0..15 -> units [8w, 8w+8)
    const int ln  = tid & 31;
    const int cta = blockIdx.x;
    const bool is_ball = (cta >= PCTAS);

    const float* wih_ = is_ball ? b_wih : p_wih;
    const float* whh_ = is_ball ? b_whh : p_whh;
    const float* bih_ = is_ball ? b_bih : p_bih;
    const float* bhh_ = is_ball ? b_bhh : p_bhh;
    const float* xsrc = is_ball ? xb : xp;
    const int s0    = is_ball ? (cta - PCTAS) * SEQS : cta * SEQS;
    const int gbase = is_ball ? NPLAYER + s0 : s0;

    // ---- zero both h buffers, stage x ----
    for (int i = tid; i < 2 * SEQS * BS / 2; i += THREADS)
        reinterpret_cast<uint32_t*>(Bsm)[i] = 0;
    for (int i = tid; i < Tt * SEQS; i += THREADS) {
        int s = i >> 7, t = i & 127;
        xs[t * SEQS + s] = *reinterpret_cast<const float2*>(
            xsrc + (size_t)(s0 + s) * 256 + t * 2);
    }

    const int r0 = ln >> 2;            // 0..7
    const int c0 = (ln & 3) * 2;       // 0,2,4,6
    const int u  = w * 8 + r0;         // hidden unit owned by this thread

    // ---- A fragments: mt0 rows = {i(u), f(u)}, mt1 rows = {g(u), o(u)} ----
    // fragment: a0,a2 = row r0 (gate A), a1,a3 = row r0+8 (gate B)
    uint32_t Af[2][NKT][4];
    #pragma unroll
    for (int mt = 0; mt < 2; mt++) {
        const float* wrA = whh_ + (size_t)((mt * 2 + 0) * Hh + u) * Hh;  // i or g
        const float* wrB = whh_ + (size_t)((mt * 2 + 1) * Hh + u) * Hh;  // f or o
        #pragma unroll
        for (int kt = 0; kt < NKT; kt++) {
            const int k = kt * 16 + c0;
            float2 aA0 = *reinterpret_cast<const float2*>(wrA + k);
            float2 aB0 = *reinterpret_cast<const float2*>(wrB + k);
            float2 aA1 = *reinterpret_cast<const float2*>(wrA + k + 8);
            float2 aB1 = *reinterpret_cast<const float2*>(wrB + k + 8);
            Af[mt][kt][0] = h2pack(aA0.x, aA0.y);
            Af[mt][kt][1] = h2pack(aB0.x, aB0.y);
            Af[mt][kt][2] = h2pack(aA1.x, aA1.y);
            Af[mt][kt][3] = h2pack(aB1.x, aB1.y);
        }
    }

    // ---- per-gate x-weights and bias for unit u ----
    float wx0[4], wx1[4], bsr[4];
    #pragma unroll
    for (int q = 0; q < 4; q++) {
        const int g = q * Hh + u;
        wx0[q] = wih_[g * 2 + 0];
        wx1[q] = wih_[g * 2 + 1];
        bsr[q] = bih_[g] + bhh_[g];
    }

    // c-state: 4 seqs {c0, c0+1, c0+8, c0+9} for unit u
    float c[4] = {0.f, 0.f, 0.f, 0.f};

    __syncthreads();

    for (int t = 0; t < Tt; t++) {
        const __half* Bcur = Bsm + (t & 1) * (SEQS * BS);
        __half*       Bnxt = Bsm + ((t + 1) & 1) * (SEQS * BS);

        // ---- D init: bias + exact fp32 x-projection ----
        // D[mt][nt][e]: e 0,1 = gate A (row r0) cols c0,c0+1; e 2,3 = gate B.
        float D[2][2][4];
        #pragma unroll
        for (int nt = 0; nt < 2; nt++) {
            #pragma unroll
            for (int e1 = 0; e1 < 2; e1++) {
                const int s = nt * 8 + c0 + e1;
                const float2 x = xs[t * SEQS + s];
                D[0][nt][e1]     = fmaf(wx1[0], x.y, fmaf(wx0[0], x.x, bsr[0]));
                D[0][nt][2 + e1] = fmaf(wx1[1], x.y, fmaf(wx0[1], x.x, bsr[1]));
                D[1][nt][e1]     = fmaf(wx1[2], x.y, fmaf(wx0[2], x.x, bsr[2]));
                D[1][nt][2 + e1] = fmaf(wx1[3], x.y, fmaf(wx0[3], x.x, bsr[3]));
            }
        }

        // ---- recurrent GEMM over h (K=128) ----
        #pragma unroll
        for (int kt = 0; kt < NKT; kt++) {
            const int kh = kt * 16 + c0;
            const __half* bp0 = Bcur + r0 * BS + kh;
            const __half* bp1 = bp0 + 8 * BS;
            const uint32_t b00 = *reinterpret_cast<const uint32_t*>(bp0);
            const uint32_t b01 = *reinterpret_cast<const uint32_t*>(bp0 + 8);
            const uint32_t b10 = *reinterpret_cast<const uint32_t*>(bp1);
            const uint32_t b11 = *reinterpret_cast<const uint32_t*>(bp1 + 8);
            mma16816(D[0][0], Af[0][kt], b00, b01);
            mma16816(D[0][1], Af[0][kt], b10, b11);
            mma16816(D[1][0], Af[1][kt], b00, b01);
            mma16816(D[1][1], Af[1][kt], b10, b11);
        }

        // ---- in-register LSTM cell update: all 4 gates local ----
        #pragma unroll
        for (int j = 0; j < 4; j++) {
            const int nt = j >> 1, e1 = j & 1;
            const int m  = nt * 8 + c0 + e1;
            const float gi = sigap(D[0][nt][e1]);
            const float gf = sigap(D[0][nt][2 + e1]);
            const float gg = tanhap(D[1][nt][e1]);
            const float go = sigap(D[1][nt][2 + e1]);
            c[j] = gf * c[j] + gi * gg;
            const float h = go * tanhap(c[j]);
            Bnxt[m * BS + u] = __float2half(h);
            if (t == Tt - 1)
                g_hid[(size_t)(gbase + m) * Hh + u] = h;
        }
        __syncthreads();   // h(t+1) visible before anyone reads Bnxt
    }
}

// FC: 128 blocks = (batch b, half of 22 players). fc_w + hidden states in smem.
#define FC_THREADS 448
__global__ __launch_bounds__(FC_THREADS)
void fc_kernel(const float* __restrict__ fc_w,
               const float* __restrict__ fc_b,
               float* __restrict__ out)
{
    __shared__ float fw[40 * 258];
    __shared__ float ph[11 * 128];
    __shared__ float ball[128];

    const int bx   = blockIdx.x;
    const int b    = bx >> 1;
    const int half = bx & 1;
    const int tid  = threadIdx.x;

    for (int idx = tid; idx < 40 * 256; idx += FC_THREADS) {
        int j = idx >> 8, k = idx & 255;
        fw[j * 258 + k] = fc_w[idx];
    }
    for (int idx = tid; idx < 11 * 128; idx += FC_THREADS) {
        int p = idx >> 7, k = idx & 127;
        ph[idx] = g_hid[(b * 22 + half * 11 + p) * Hh + k];
    }
    for (int idx = tid; idx < 128; idx += FC_THREADS)
        ball[idx] = g_hid[(NPLAYER + b) * Hh + idx];
    __syncthreads();

    if (tid < 440) {
        const int p = tid / 40;
        const int j = tid - p * 40;
        const float2* php  = (const float2*)(ph + p * 128);
        const float2* blp  = (const float2*)(ball);
        const float2* fwp0 = (const float2*)(fw + j * 258);
        const float2* fwp1 = (const float2*)(fw + j * 258 + 128);
        float acc = fc_b[j];
        #pragma unroll 8
        for (int k2 = 0; k2 < 64; k2++) {
            float2 hp = php[k2], hb = blp[k2];
            float2 w0 = fwp0[k2], w1 = fwp1[k2];
            acc += hp.x * w0.x + hp.y * w0.y + hb.x * w1.x + hb.y * w1.y;
        }
        out[(b * 22 + half * 11 + p) * 40 + j] = acc;
    }
}

extern "C" void kernel_launch(void* const* d_in, const int* in_sizes, int n_in,
                              void* d_out, int out_size)
{
    const float* xp    = (const float*)d_in[0];
    const float* xb    = (const float*)d_in[1];
    const float* p_wih = (const float*)d_in[2];
    const float* p_whh = (const float*)d_in[3];
    const float* p_bih = (const float*)d_in[4];
    const float* p_bhh = (const float*)d_in[5];
    const float* b_wih = (const float*)d_in[6];
    const float* b_whh = (const float*)d_in[7];
    const float* b_bih = (const float*)d_in[8];
    const float* b_bhh = (const float*)d_in[9];
    const float* fc_w  = (const float*)d_in[10];
    const float* fc_b  = (const float*)d_in[11];
    float* out = (float*)d_out;

    lstm_hmma_kernel<<<NCTAS, THREADS>>>(xp, xb,
                                         p_wih, p_whh, p_bih, p_bhh,
                                         b_wih, b_whh, b_bih, b_bhh);
    fc_kernel<<<128, FC_THREADS>>>(fc_w, fc_b, out);
}